// round 1
// baseline (speedup 1.0000x reference)
#include <cuda_runtime.h>
#include <cstdint>

#define N_NODES 50000
#define X_DIMS 256
#define Y_DIMS 64

// ---------------- scratch (no cudaMalloc allowed) ----------------
__device__ int   g_row_ptr[N_NODES + 1];
__device__ float g_x1[(size_t)N_NODES * X_DIMS];
__device__ float g_x2[(size_t)N_NODES * X_DIMS];
__device__ float g_y1[(size_t)N_NODES * Y_DIMS];
__device__ float g_y2[(size_t)N_NODES * Y_DIMS];

// ---------------- CSR row_ptr from sorted COO row ----------------
__global__ void build_rowptr_kernel(const int* __restrict__ row, int E, int n)
{
    int r = blockIdx.x * blockDim.x + threadIdx.x;
    if (r > n) return;
    int lo = 0, hi = E;
    while (lo < hi) {
        int mid = (lo + hi) >> 1;
        if (row[mid] < r) lo = mid + 1; else hi = mid;
    }
    g_row_ptr[r] = lo;
}

// ---------------- vector row load/store helpers ----------------
__device__ __forceinline__ void load_row(const float* __restrict__ p, int lane, float (&v)[8])
{
    float4 a = *(const float4*)(p + lane * 4);
    float4 b = *(const float4*)(p + 128 + lane * 4);
    v[0]=a.x; v[1]=a.y; v[2]=a.z; v[3]=a.w;
    v[4]=b.x; v[5]=b.y; v[6]=b.z; v[7]=b.w;
}
__device__ __forceinline__ void load_row(const float* __restrict__ p, int lane, float (&v)[2])
{
    float2 a = *(const float2*)(p + lane * 2);
    v[0]=a.x; v[1]=a.y;
}
__device__ __forceinline__ void store_row(float* __restrict__ p, int lane, const float (&v)[8])
{
    *(float4*)(p + lane * 4)       = make_float4(v[0], v[1], v[2], v[3]);
    *(float4*)(p + 128 + lane * 4) = make_float4(v[4], v[5], v[6], v[7]);
}
__device__ __forceinline__ void store_row(float* __restrict__ p, int lane, const float (&v)[2])
{
    *(float2*)(p + lane * 2) = make_float2(v[0], v[1]);
}

// ---------------- fused adaptive-RBF row-normalized SpMM ----------------
// One warp per destination row. out[r] = (sum_e val_e * f[col_e]) / (sum_e val_e)
// val_e = exp(-||f[r]-f[col_e]||^2 / sigma^2); rows without edges -> 0.
template <int D>
__global__ void __launch_bounds__(256) prop_kernel(
    const float* __restrict__ feats,
    const int*   __restrict__ col,
    const float* __restrict__ sigmas, int sidx,
    float* __restrict__ out, int n)
{
    constexpr int C = D / 32;           // floats per lane
    int gw   = (int)((blockIdx.x * 256u + threadIdx.x) >> 5);
    int lane = threadIdx.x & 31;
    if (gw >= n) return;

    float sg = sigmas[sidx];
    float inv_s2 = 1.0f / (sg * sg);

    int e0 = g_row_ptr[gw];
    int e1 = g_row_ptr[gw + 1];

    float fr[C], acc[C];
    load_row(feats + (size_t)gw * D, lane, fr);
#pragma unroll
    for (int i = 0; i < C; i++) acc[i] = 0.0f;
    float den = 0.0f;

    for (int e = e0; e < e1; e++) {
        int c = __ldg(col + e);
        float fc[C];
        load_row(feats + (size_t)c * D, lane, fc);
        float pw = 0.0f;
#pragma unroll
        for (int i = 0; i < C; i++) {
            float d = fr[i] - fc[i];
            pw = fmaf(d, d, pw);
        }
#pragma unroll
        for (int o = 16; o > 0; o >>= 1)
            pw += __shfl_xor_sync(0xffffffffu, pw, o);
        float val = expf(-pw * inv_s2);
        den += val;
#pragma unroll
        for (int i = 0; i < C; i++) acc[i] = fmaf(val, fc[i], acc[i]);
    }

    float inv = (den > 0.0f) ? (1.0f / den) : 0.0f;
#pragma unroll
    for (int i = 0; i < C; i++) acc[i] *= inv;
    store_row(out + (size_t)gw * D, lane, acc);
}

// ---------------- fused segmented GEMM: [M,896] @ [896,64] ----------------
// A is the virtual concat [x | x1 | x2 | y1 | y2]; segments read directly.
#define BM 128
#define BN 64
#define BK 32
#define APITCH (BM + 4)   // 132: k*132*4 = 528B, 16B-aligned for LDS.128

__global__ void __launch_bounds__(256) gemm_kernel(
    const float* __restrict__ x,
    const float* __restrict__ x1,
    const float* __restrict__ x2,
    const float* __restrict__ y1,
    const float* __restrict__ y2,
    const float* __restrict__ W,
    float* __restrict__ out, int M)
{
    __shared__ float As[BK][APITCH];   // k-major (transposed) A tile
    __shared__ float Bs[BK][BN];

    int tid = threadIdx.x;
    int tx = tid & 15;    // 16 col-groups * 4 cols
    int ty = tid >> 4;    // 16 row-groups * 8 rows
    int row0 = blockIdx.x * BM;

    float c[8][4];
#pragma unroll
    for (int i = 0; i < 8; i++)
#pragma unroll
        for (int j = 0; j < 4; j++) c[i][j] = 0.0f;

    const float* segs[5]   = { x, x1, x2, y1, y2 };
    const int    widths[5] = { X_DIMS, X_DIMS, X_DIMS, Y_DIMS, Y_DIMS };

    int kglobal = 0;
    for (int s = 0; s < 5; s++) {
        const float* A = segs[s];
        int width = widths[s];
        for (int kc = 0; kc < width; kc += BK) {
            // --- load A tile (transposed into smem) ---
            int kg = (tid & 7) * 4;
#pragma unroll
            for (int i = 0; i < 4; i++) {
                int r = (tid >> 3) + 32 * i;
                int grow = row0 + r;
                float4 v = make_float4(0.f, 0.f, 0.f, 0.f);
                if (grow < M)
                    v = *(const float4*)(A + (size_t)grow * width + kc + kg);
                As[kg + 0][r] = v.x;
                As[kg + 1][r] = v.y;
                As[kg + 2][r] = v.z;
                As[kg + 3][r] = v.w;
            }
            // --- load B tile (W rows kglobal+kc .. +BK) ---
#pragma unroll
            for (int i = 0; i < 2; i++) {
                int k = (tid >> 4) + 16 * i;
                int j = (tid & 15) * 4;
                float4 v = *(const float4*)(W + (size_t)(kglobal + kc + k) * BN + j);
                *(float4*)&Bs[k][j] = v;
            }
            __syncthreads();
            // --- compute ---
#pragma unroll
            for (int k = 0; k < BK; k++) {
                float4 a0 = *(const float4*)&As[k][ty * 8];
                float4 a1 = *(const float4*)&As[k][ty * 8 + 4];
                float4 b  = *(const float4*)&Bs[k][tx * 4];
                float av[8] = { a0.x, a0.y, a0.z, a0.w, a1.x, a1.y, a1.z, a1.w };
                float bv[4] = { b.x, b.y, b.z, b.w };
#pragma unroll
                for (int i = 0; i < 8; i++)
#pragma unroll
                    for (int j = 0; j < 4; j++)
                        c[i][j] = fmaf(av[i], bv[j], c[i][j]);
            }
            __syncthreads();
        }
        kglobal += width;
    }

    // --- store ---
#pragma unroll
    for (int i = 0; i < 8; i++) {
        int grow = row0 + ty * 8 + i;
        if (grow < M)
            *(float4*)(out + (size_t)grow * BN + tx * 4) =
                make_float4(c[i][0], c[i][1], c[i][2], c[i][3]);
    }
}

// ---------------- launch ----------------
extern "C" void kernel_launch(void* const* d_in, const int* in_sizes, int n_in,
                              void* d_out, int out_size)
{
    const float* x   = (const float*)d_in[0];   // [N, 256]
    const float* y   = (const float*)d_in[1];   // [N, 64]
    const float* W   = (const float*)d_in[2];   // [896, 64]
    const float* sig = (const float*)d_in[3];   // [4]
    const int*   row = (const int*)  d_in[4];   // [E] sorted
    const int*   col = (const int*)  d_in[5];   // [E]

    int N = in_sizes[0] / X_DIMS;
    int E = in_sizes[4];

    float *px1, *px2, *py1, *py2;
    cudaGetSymbolAddress((void**)&px1, g_x1);
    cudaGetSymbolAddress((void**)&px2, g_x2);
    cudaGetSymbolAddress((void**)&py1, g_y1);
    cudaGetSymbolAddress((void**)&py2, g_y2);

    build_rowptr_kernel<<<(N + 1 + 255) / 256, 256>>>(row, E, N);

    int pb = (N * 32 + 255) / 256;   // one warp per row
    prop_kernel<X_DIMS><<<pb, 256>>>(x,   col, sig, 0, px1, N);
    prop_kernel<X_DIMS><<<pb, 256>>>(px1, col, sig, 1, px2, N);
    prop_kernel<Y_DIMS><<<pb, 256>>>(y,   col, sig, 2, py1, N);
    prop_kernel<Y_DIMS><<<pb, 256>>>(py1, col, sig, 3, py2, N);

    gemm_kernel<<<(N + BM - 1) / BM, 256>>>(x, px1, px2, py1, py2, W,
                                            (float*)d_out, N);
}

// round 2
// speedup vs baseline: 1.4164x; 1.4164x over previous
#include <cuda_runtime.h>
#include <cstdint>

#define N_NODES 50000
#define X_DIMS 256
#define Y_DIMS 64

// ---------------- scratch (no cudaMalloc allowed) ----------------
__device__ int   g_row_ptr[N_NODES + 1];
__device__ float g_x1[(size_t)N_NODES * X_DIMS];
__device__ float g_x2[(size_t)N_NODES * X_DIMS];
__device__ float g_y1[(size_t)N_NODES * Y_DIMS];
__device__ float g_y2[(size_t)N_NODES * Y_DIMS];

// ---------------- CSR row_ptr from sorted COO row ----------------
__global__ void build_rowptr_kernel(const int* __restrict__ row, int E, int n)
{
    int r = blockIdx.x * blockDim.x + threadIdx.x;
    if (r > n) return;
    int lo = 0, hi = E;
    while (lo < hi) {
        int mid = (lo + hi) >> 1;
        if (row[mid] < r) lo = mid + 1; else hi = mid;
    }
    g_row_ptr[r] = lo;
}

// ---------------- vector row load/store helpers ----------------
__device__ __forceinline__ void load_row(const float* __restrict__ p, int lane, float (&v)[8])
{
    float4 a = *(const float4*)(p + lane * 4);
    float4 b = *(const float4*)(p + 128 + lane * 4);
    v[0]=a.x; v[1]=a.y; v[2]=a.z; v[3]=a.w;
    v[4]=b.x; v[5]=b.y; v[6]=b.z; v[7]=b.w;
}
__device__ __forceinline__ void load_row(const float* __restrict__ p, int lane, float (&v)[2])
{
    float2 a = *(const float2*)(p + lane * 2);
    v[0]=a.x; v[1]=a.y;
}
__device__ __forceinline__ void store_row(float* __restrict__ p, int lane, const float (&v)[8])
{
    *(float4*)(p + lane * 4)       = make_float4(v[0], v[1], v[2], v[3]);
    *(float4*)(p + 128 + lane * 4) = make_float4(v[4], v[5], v[6], v[7]);
}
__device__ __forceinline__ void store_row(float* __restrict__ p, int lane, const float (&v)[2])
{
    *(float2*)(p + lane * 2) = make_float2(v[0], v[1]);
}

// ---------------- fused adaptive-RBF row-normalized SpMM ----------------
// One warp per destination row, U edges in flight (independent latency chains).
template <int D, int U>
__global__ void __launch_bounds__(256) prop_kernel(
    const float* __restrict__ feats,
    const int*   __restrict__ col,
    const float* __restrict__ sigmas, int sidx,
    float* __restrict__ out, int n)
{
    constexpr int C = D / 32;           // floats per lane
    int gw   = (int)((blockIdx.x * 256u + threadIdx.x) >> 5);
    int lane = threadIdx.x & 31;
    if (gw >= n) return;

    float sg = sigmas[sidx];
    float inv_s2 = 1.0f / (sg * sg);

    int e0 = g_row_ptr[gw];
    int e1 = g_row_ptr[gw + 1];

    float fr[C], acc[C];
    load_row(feats + (size_t)gw * D, lane, fr);
#pragma unroll
    for (int i = 0; i < C; i++) acc[i] = 0.0f;
    float den = 0.0f;

    int e = e0;
    // --- main unrolled loop: U independent edges in flight ---
    for (; e + U <= e1; e += U) {
        int cs[U];
#pragma unroll
        for (int j = 0; j < U; j++) cs[j] = __ldg(col + e + j);

        float fc[U][C];
#pragma unroll
        for (int j = 0; j < U; j++)
            load_row(feats + (size_t)cs[j] * D, lane, fc[j]);

        float pw[U];
#pragma unroll
        for (int j = 0; j < U; j++) {
            float p = 0.0f;
#pragma unroll
            for (int i = 0; i < C; i++) {
                float d = fr[i] - fc[j][i];
                p = fmaf(d, d, p);
            }
            pw[j] = p;
        }
        // interleaved butterfly reductions (latencies overlap across j)
#pragma unroll
        for (int o = 16; o > 0; o >>= 1) {
#pragma unroll
            for (int j = 0; j < U; j++)
                pw[j] += __shfl_xor_sync(0xffffffffu, pw[j], o);
        }
#pragma unroll
        for (int j = 0; j < U; j++) {
            float val = expf(-pw[j] * inv_s2);
            den += val;
#pragma unroll
            for (int i = 0; i < C; i++) acc[i] = fmaf(val, fc[j][i], acc[i]);
        }
    }
    // --- tail ---
    for (; e < e1; e++) {
        int c = __ldg(col + e);
        float fc[C];
        load_row(feats + (size_t)c * D, lane, fc);
        float p = 0.0f;
#pragma unroll
        for (int i = 0; i < C; i++) {
            float d = fr[i] - fc[i];
            p = fmaf(d, d, p);
        }
#pragma unroll
        for (int o = 16; o > 0; o >>= 1)
            p += __shfl_xor_sync(0xffffffffu, p, o);
        float val = expf(-p * inv_s2);
        den += val;
#pragma unroll
        for (int i = 0; i < C; i++) acc[i] = fmaf(val, fc[i], acc[i]);
    }

    float inv = (den > 0.0f) ? (1.0f / den) : 0.0f;
#pragma unroll
    for (int i = 0; i < C; i++) acc[i] *= inv;
    store_row(out + (size_t)gw * D, lane, acc);
}

// ---------------- tf32 tensor-core GEMM: [M,896] @ [896,64] ----------------
#define BM 128
#define BN 64
#define BK 32
#define AP (BK + 4)    // A pitch 36 words -> 144B rows (16B aligned), frag loads conflict-free
#define BP (BN + 8)    // B pitch 72 words -> 288B rows (16B aligned), frag loads conflict-free

__device__ __forceinline__ uint32_t f2tf32(float f)
{
    uint32_t u;
    asm("cvt.rna.tf32.f32 %0, %1;" : "=r"(u) : "f"(f));
    return u;
}

__device__ __forceinline__ void mma_tf32(float (&c)[4], const uint32_t (&a)[4], const uint32_t (&b)[2])
{
    asm volatile(
        "mma.sync.aligned.m16n8k8.row.col.f32.tf32.tf32.f32 "
        "{%0,%1,%2,%3}, {%4,%5,%6,%7}, {%8,%9}, {%0,%1,%2,%3};\n"
        : "+f"(c[0]), "+f"(c[1]), "+f"(c[2]), "+f"(c[3])
        : "r"(a[0]), "r"(a[1]), "r"(a[2]), "r"(a[3]), "r"(b[0]), "r"(b[1]));
}

__global__ void __launch_bounds__(256) gemm_tf32_kernel(
    const float* __restrict__ x,
    const float* __restrict__ x1,
    const float* __restrict__ x2,
    const float* __restrict__ y1,
    const float* __restrict__ y2,
    const float* __restrict__ W,
    float* __restrict__ out, int M)
{
    __shared__ float As[BM][AP];   // m-major, 18432 B
    __shared__ float Bs[BK][BP];   // k-major,  9216 B

    int tid  = threadIdx.x;
    int lane = tid & 31;
    int wid  = tid >> 5;
    int wm = (wid >> 1) * 32;      // warp M offset (0,32,64,96)
    int wn = (wid & 1) * 32;       // warp N offset (0,32)
    int g  = lane >> 2;            // 0..7
    int tk = lane & 3;             // 0..3
    int row0 = blockIdx.x * BM;

    float c[2][4][4];
#pragma unroll
    for (int mt = 0; mt < 2; mt++)
#pragma unroll
        for (int nt = 0; nt < 4; nt++)
#pragma unroll
            for (int q = 0; q < 4; q++) c[mt][nt][q] = 0.0f;

    const float* segs[5]   = { x, x1, x2, y1, y2 };
    const int    widths[5] = { X_DIMS, X_DIMS, X_DIMS, Y_DIMS, Y_DIMS };

    int kglobal = 0;
    for (int s = 0; s < 5; s++) {
        const float* A = segs[s];
        int width = widths[s];
        for (int kc = 0; kc < width; kc += BK) {
            // --- A tile: 128 rows x 32 floats, direct (no transpose) ---
#pragma unroll
            for (int i = 0; i < 4; i++) {
                int idx = i * 256 + tid;
                int r  = idx >> 3;
                int kg = (idx & 7) * 4;
                int grow = row0 + r;
                float4 v = make_float4(0.f, 0.f, 0.f, 0.f);
                if (grow < M)
                    v = *(const float4*)(A + (size_t)grow * width + kc + kg);
                *(float4*)&As[r][kg] = v;
            }
            // --- B tile: 32 rows x 64 floats ---
#pragma unroll
            for (int i = 0; i < 2; i++) {
                int idx = i * 256 + tid;
                int k = idx >> 4;
                int j = (idx & 15) * 4;
                float4 v = *(const float4*)(W + (size_t)(kglobal + kc + k) * BN + j);
                *(float4*)&Bs[k][j] = v;
            }
            __syncthreads();

#pragma unroll
            for (int kk = 0; kk < BK; kk += 8) {
                uint32_t a[2][4];
#pragma unroll
                for (int mt = 0; mt < 2; mt++) {
                    int mrow = wm + mt * 16 + g;
                    a[mt][0] = f2tf32(As[mrow][kk + tk]);
                    a[mt][1] = f2tf32(As[mrow + 8][kk + tk]);
                    a[mt][2] = f2tf32(As[mrow][kk + tk + 4]);
                    a[mt][3] = f2tf32(As[mrow + 8][kk + tk + 4]);
                }
                uint32_t b[4][2];
#pragma unroll
                for (int nt = 0; nt < 4; nt++) {
                    int ncol = wn + nt * 8 + g;
                    b[nt][0] = f2tf32(Bs[kk + tk][ncol]);
                    b[nt][1] = f2tf32(Bs[kk + tk + 4][ncol]);
                }
#pragma unroll
                for (int mt = 0; mt < 2; mt++)
#pragma unroll
                    for (int nt = 0; nt < 4; nt++)
                        mma_tf32(c[mt][nt], a[mt], b[nt]);
            }
            __syncthreads();
        }
        kglobal += width;
    }

    // --- store: c0,c1 -> (row, 2tk..2tk+1), c2,c3 -> (row+8, ...) ---
#pragma unroll
    for (int mt = 0; mt < 2; mt++) {
#pragma unroll
        for (int nt = 0; nt < 4; nt++) {
            int r0 = row0 + wm + mt * 16 + g;
            int cc = wn + nt * 8 + 2 * tk;
            if (r0 < M)
                *(float2*)(out + (size_t)r0 * BN + cc) = make_float2(c[mt][nt][0], c[mt][nt][1]);
            if (r0 + 8 < M)
                *(float2*)(out + (size_t)(r0 + 8) * BN + cc) = make_float2(c[mt][nt][2], c[mt][nt][3]);
        }
    }
}

// ---------------- launch ----------------
extern "C" void kernel_launch(void* const* d_in, const int* in_sizes, int n_in,
                              void* d_out, int out_size)
{
    const float* x   = (const float*)d_in[0];   // [N, 256]
    const float* y   = (const float*)d_in[1];   // [N, 64]
    const float* W   = (const float*)d_in[2];   // [896, 64]
    const float* sig = (const float*)d_in[3];   // [4]
    const int*   row = (const int*)  d_in[4];   // [E] sorted
    const int*   col = (const int*)  d_in[5];   // [E]

    int N = in_sizes[0] / X_DIMS;
    int E = in_sizes[4];

    float *px1, *px2, *py1, *py2;
    cudaGetSymbolAddress((void**)&px1, g_x1);
    cudaGetSymbolAddress((void**)&px2, g_x2);
    cudaGetSymbolAddress((void**)&py1, g_y1);
    cudaGetSymbolAddress((void**)&py2, g_y2);

    build_rowptr_kernel<<<(N + 1 + 255) / 256, 256>>>(row, E, N);

    int pb = (N * 32 + 255) / 256;   // one warp per row
    prop_kernel<X_DIMS, 2><<<pb, 256>>>(x,   col, sig, 0, px1, N);
    prop_kernel<X_DIMS, 2><<<pb, 256>>>(px1, col, sig, 1, px2, N);
    prop_kernel<Y_DIMS, 4><<<pb, 256>>>(y,   col, sig, 2, py1, N);
    prop_kernel<Y_DIMS, 4><<<pb, 256>>>(py1, col, sig, 3, py2, N);

    gemm_tf32_kernel<<<(N + BM - 1) / BM, 256>>>(x, px1, px2, py1, py2, W,
                                                 (float*)d_out, N);
}